// round 7
// baseline (speedup 1.0000x reference)
#include <cuda_runtime.h>
#include <cfloat>
#include <math.h>

// Problem constants (fixed by the benchmark)
#define BB   2
#define CC   2
#define NN   1024
#define HH   8
#define FF   64
#define FIN2 (HH*FF)          // 512
#define NSL  (BB*CC*HH)       // 32 attention slices
#define L2E  1.4426950408889634f

// dynamic smem layout for attn kernel (bytes)
#define SM_HP    0            // float hp_s[64*64]            16384
#define SM_E2    16384        // float2 e2_s[64*66]           33792 (row stride 66)
#define SM_D     50176        // float d_s[1024]               4096
#define SM_SRML  54272        // float2 srml_s[64]              512
#define SM_LINV  54784        // float linv_s[64]               256
#define SM_ATTN  55040

// ---------------- scratch (device globals: allocation-free) ----------------
__device__ unsigned int g_mask[BB*NN*(NN/32)];            // packed valid-edge bits (incl self loops)
__device__ float g_hp[(size_t)NSL*NN*FF];                 // h_prime for current layer
__device__ float g_s [NSL*NN];                            // src scores
__device__ float g_d [NSL*NN];                            // dst scores
__device__ float g_rml[NSL*NN];                           // rowmax * log2(e)
__device__ float g_x1[(size_t)BB*CC*NN*FIN2];             // layer-1 output (elu, head-flattened)
__device__ float g_o2[(size_t)NSL*NN*FF];                 // layer-2 attention output (pre head-mean)

// ---------------- helpers ----------------
union f4u { float4 f; unsigned long long u[2]; float e[4]; };

__device__ __forceinline__ unsigned long long pack2(float a, float b){
    unsigned long long r;
    asm("mov.b64 %0, {%1,%2};" : "=l"(r) : "f"(a), "f"(b));
    return r;
}
__device__ __forceinline__ void ffma2(unsigned long long &d, unsigned long long a, unsigned long long b){
    asm("fma.rn.f32x2 %0, %1, %2, %0;" : "+l"(d) : "l"(a), "l"(b));
}
__device__ __forceinline__ float ex2f(float x){
    float r; asm("ex2.approx.f32 %0, %1;" : "=f"(r) : "f"(x)); return r;
}
__device__ __forceinline__ void cpasync16(unsigned smem, const void* g){
    asm volatile("cp.async.cg.shared.global [%0], [%1], 16;" :: "r"(smem), "l"(g));
}
__device__ __forceinline__ void cpasync_commit(){ asm volatile("cp.async.commit_group;"); }
__device__ __forceinline__ void cpasync_wait0(){ asm volatile("cp.async.wait_group 0;"); }

// ---------------- kernel 1: pack adjacency (+self loops) into bitmask ----------------
__global__ void pack_mask_kernel(const int* __restrict__ adj){
    int n = blockIdx.x, b = blockIdx.y, m = threadIdx.x;   // block of 1024 threads
    bool valid = (adj[((size_t)b*NN + n)*NN + m] != 0) || (m == n);
    unsigned bits = __ballot_sync(0xffffffffu, valid);
    if ((m & 31) == 0) g_mask[((size_t)b*NN + n)*32 + (m >> 5)] = bits;
}

// ---------------- kernel 2: h_prime = x @ w  (+ tanh -> s,d scores) ----------------
// grid (NSL, NN/64), block 256. Thread tile 4 rows x 4 feats, f32x2 FMAs.
template<int FIN, bool FROMX1>
__global__ __launch_bounds__(256, 3) void gemm_sd_kernel(
    const float* __restrict__ xin, const float* __restrict__ w,
    const float* __restrict__ a_src, const float* __restrict__ a_dst)
{
    __shared__ float xs[64*64];     // [n][k]
    __shared__ float ws[64*64];     // [k][f]
    __shared__ float as_s[64], ad_s[64];

    const int sl = blockIdx.x, n0 = blockIdx.y*64;
    const int b = sl/(CC*HH), c = (sl/HH)%CC, h = sl%HH;
    const int tid = threadIdx.x, lane = tid & 31;
    const int tx = tid & 15, ty = tid >> 4;        // feats 4tx.., rows 4ty..

    const float* x = FROMX1 ? (const float*)g_x1 : xin;
    const float* xbase = x + ((size_t)(b*CC + c)*NN + n0)*FIN;
    const float* wbase = w + (size_t)(c*HH + h)*FIN*FF;

    if (tid < 64){
        int ch = (c*HH + h)*FF;
        as_s[tid] = a_src[ch + tid];
        ad_s[tid] = a_dst[ch + tid];
    }

    f4u acc[4];
    #pragma unroll
    for (int j = 0; j < 4; j++){ acc[j].u[0] = 0ull; acc[j].u[1] = 0ull; }

    for (int kc = 0; kc < FIN/64; kc++){
        __syncthreads();
        // stage x tile [64n x 64k] (coalesced float4)
        #pragma unroll
        for (int p = 0; p < 4; p++){
            int n = (tid >> 4) + 16*p;
            ((float4*)xs)[n*16 + (tid & 15)] =
                *(const float4*)&xbase[(size_t)n*FIN + kc*64 + 4*(tid & 15)];
        }
        // stage w tile [64k x 64f] (contiguous)
        const float4* wsrc = (const float4*)(wbase + (size_t)kc*64*FF);
        #pragma unroll
        for (int q = 0; q < 4; q++) ((float4*)ws)[tid + 256*q] = wsrc[tid + 256*q];
        __syncthreads();

        const float4* xs4 = (const float4*)xs;
        const float4* ws4 = (const float4*)ws;
        #pragma unroll
        for (int kk = 0; kk < 16; kk++){
            f4u xr[4];
            #pragma unroll
            for (int j = 0; j < 4; j++) xr[j].f = xs4[(4*ty + j)*16 + kk];
            #pragma unroll
            for (int i = 0; i < 4; i++){
                f4u wv; wv.f = ws4[(4*kk + i)*16 + tx];
                #pragma unroll
                for (int j = 0; j < 4; j++){
                    unsigned long long xx = pack2(xr[j].e[i], xr[j].e[i]);
                    ffma2(acc[j].u[0], wv.u[0], xx);
                    ffma2(acc[j].u[1], wv.u[1], xx);
                }
            }
        }
    }

    // epilogue: write h_prime + tanh-weighted scores
    #pragma unroll
    for (int j = 0; j < 4; j++){
        const int n = n0 + 4*ty + j;
        *(float4*)&g_hp[((size_t)sl*NN + n)*FF + 4*tx] = acc[j].f;
        float sp = 0.f, dp = 0.f;
        #pragma unroll
        for (int i = 0; i < 4; i++){
            float t = tanhf(acc[j].e[i]);
            sp = fmaf(t, as_s[4*tx + i], sp);
            dp = fmaf(t, ad_s[4*tx + i], dp);
        }
        #pragma unroll
        for (int o = 8; o; o >>= 1){
            sp += __shfl_xor_sync(0xffffffffu, sp, o);
            dp += __shfl_xor_sync(0xffffffffu, dp, o);
        }
        if ((lane & 15) == 0){ g_s[sl*NN + n] = sp; g_d[sl*NN + n] = dp; }
    }
}

// ---------------- kernel 3: exact row max (leaky is monotone => leaky(s + dmax)) ----------------
// grid (NSL, NN/128), block 256 (8 warps x 16 rows).
__global__ __launch_bounds__(256) void rowmax_kernel(){
    __shared__ float d_sw[1024];                 // d rotated for conflict-free column scans
    const int sl = blockIdx.x, n0 = blockIdx.y*128;
    const int b = sl/(CC*HH);
    const int tid = threadIdx.x, lane = tid & 31, wrp = tid >> 5;

    for (int i = tid; i < 1024; i += 256){
        int w = i >> 5, j = i & 31;
        d_sw[(w << 5) + ((j + w) & 31)] = g_d[sl*NN + i];
    }
    __syncthreads();

    const unsigned* mb = g_mask + (size_t)b*NN*32;
    for (int r = 0; r < 16; r++){
        const int n = n0 + wrp*16 + r;
        unsigned word = mb[(size_t)n*32 + lane];
        float dm = -FLT_MAX;
        #pragma unroll
        for (int i = 0; i < 32; i++){
            float v = d_sw[(lane << 5) + ((i + lane) & 31)];
            if ((word >> i) & 1u) dm = fmaxf(dm, v);
        }
        #pragma unroll
        for (int o = 16; o; o >>= 1) dm = fmaxf(dm, __shfl_xor_sync(0xffffffffu, dm, o));
        if (lane == 0){
            float s = g_s[sl*NN + n];
            float r0 = s + dm; r0 = (r0 >= 0.f) ? r0 : 0.2f*r0;   // leaky(max) = max(leaky)
            g_rml[sl*NN + n] = r0 * L2E;
        }
    }
}

// ---------------- kernel 4: masked softmax + P @ h_prime (single pass, no rescale) ----------------
// grid (NSL, NN/64), block 256, 3 CTAs/SM, dynamic smem. 64 rows x 64 feats, m-tile 64.
// e stored DUPLICATED as float2{e,e} -> accumulate needs zero pack instructions:
// per 4-k chunk: 12 LDS.128 + 32 ffma2 (44 issue slots / 64 MACs).
template<bool LAYER1>
__global__ __launch_bounds__(256, 3) void attn_kernel(){
    extern __shared__ char smdyn[];
    float*  hp_s   = (float*) (smdyn + SM_HP);     // [m][f]
    float2* e2_s   = (float2*)(smdyn + SM_E2);     // [row][m] dup, stride 66
    float*  d_s    = (float*) (smdyn + SM_D);
    float2* srml_s = (float2*)(smdyn + SM_SRML);   // {s, rml}
    float*  linv_s = (float*) (smdyn + SM_LINV);

    const int sl = blockIdx.x, n0 = blockIdx.y*64;
    const int b = sl/(CC*HH), c = (sl/HH)%CC, h = sl%HH;
    const int tid = threadIdx.x, lane = tid & 31, wrp = tid >> 5;
    const int tx = tid & 15, ty = tid >> 4;
    const int row0 = wrp*8;

    for (int i = tid; i < 1024; i += 256) d_s[i] = g_d[sl*NN + i];
    if (tid < 64)
        srml_s[tid] = make_float2(g_s[sl*NN + n0 + tid], g_rml[sl*NN + n0 + tid]);

    float lsum[8];
    #pragma unroll
    for (int r = 0; r < 8; r++) lsum[r] = 0.f;

    f4u acc[4];
    #pragma unroll
    for (int j = 0; j < 4; j++){ acc[j].u[0] = 0ull; acc[j].u[1] = 0ull; }

    const unsigned* mbase = g_mask + ((size_t)b*NN + n0)*32;
    const unsigned hp_smem = (unsigned)__cvta_generic_to_shared(hp_s);

    __syncthreads();                             // d_s/srml_s ready

    for (int t = 0; t < 16; t++){
        const int m0 = t*64;

        // issue async copy of h_prime tile (overlaps with score phase below)
        const float4* hsrc = (const float4*)(g_hp + ((size_t)sl*NN + m0)*FF);
        #pragma unroll
        for (int q = 0; q < 4; q++)
            cpasync16(hp_smem + (tid + 256*q)*16, hsrc + tid + 256*q);
        cpasync_commit();

        // coalesced mask fetch: lanes 0..15 hold 8 rows x 2 words for this warp
        unsigned mword = 0u;
        if (lane < 16)
            mword = mbase[(size_t)(row0 + (lane >> 1))*32 + t*2 + (lane & 1)];

        // --- score phase (writes duplicated e pairs) ---
        const float d0 = d_s[m0 + lane];
        const float d1 = d_s[m0 + lane + 32];
        #pragma unroll
        for (int r = 0; r < 8; r++){
            const int row = row0 + r;
            unsigned mwa = __shfl_sync(0xffffffffu, mword, 2*r);
            unsigned mwb = __shfl_sync(0xffffffffu, mword, 2*r + 1);
            float2 sr = srml_s[row];
            float x0 = sr.x + d0; x0 = (x0 >= 0.f) ? x0 : 0.2f*x0;   // leaky_relu(0.2)
            float x1 = sr.x + d1; x1 = (x1 >= 0.f) ? x1 : 0.2f*x1;
            float e0 = ((mwa >> lane) & 1u) ? ex2f(fmaf(x0, L2E, -sr.y)) : 0.f;
            float e1 = ((mwb >> lane) & 1u) ? ex2f(fmaf(x1, L2E, -sr.y)) : 0.f;
            lsum[r] += e0 + e1;
            e2_s[row*66 + lane]      = make_float2(e0, e0);
            e2_s[row*66 + lane + 32] = make_float2(e1, e1);
        }

        cpasync_wait0();
        __syncthreads();                         // e2_s + hp_s ready

        // --- accumulate phase: P-tile @ h-tile, pack-free f32x2 register GEMM ---
        const float4* hp4 = (const float4*)hp_s;
        const float4* e4  = (const float4*)(smdyn + SM_E2);   // row stride 33 float4
        #pragma unroll
        for (int kk = 0; kk < 16; kk++){
            f4u wv[4];
            #pragma unroll
            for (int i = 0; i < 4; i++) wv[i].f = hp4[(4*kk + i)*16 + tx];
            #pragma unroll
            for (int j = 0; j < 4; j++){
                const float4* er = e4 + (4*ty + j)*33 + 2*kk;
                f4u ea, eb; ea.f = er[0]; eb.f = er[1];        // (e,e) pairs for k..k+3
                ffma2(acc[j].u[0], wv[0].u[0], ea.u[0]);
                ffma2(acc[j].u[1], wv[0].u[1], ea.u[0]);
                ffma2(acc[j].u[0], wv[1].u[0], ea.u[1]);
                ffma2(acc[j].u[1], wv[1].u[1], ea.u[1]);
                ffma2(acc[j].u[0], wv[2].u[0], eb.u[0]);
                ffma2(acc[j].u[1], wv[2].u[1], eb.u[0]);
                ffma2(acc[j].u[0], wv[3].u[0], eb.u[1]);
                ffma2(acc[j].u[1], wv[3].u[1], eb.u[1]);
            }
        }
        __syncthreads();                         // protect hp_s/e2_s before next tile
    }

    // reduce row sums (per-lane partials) and invert
    #pragma unroll
    for (int r = 0; r < 8; r++){
        float v = lsum[r];
        #pragma unroll
        for (int o = 16; o; o >>= 1) v += __shfl_xor_sync(0xffffffffu, v, o);
        if (lane == 0) linv_s[row0 + r] = 1.f / v;
    }
    __syncthreads();

    // epilogue
    #pragma unroll
    for (int j = 0; j < 4; j++){
        const int row = 4*ty + j, n = n0 + row;
        const float inv = linv_s[row];
        f4u o0;
        #pragma unroll
        for (int i = 0; i < 4; i++) o0.e[i] = acc[j].e[i] * inv;
        if (LAYER1){
            #pragma unroll
            for (int i = 0; i < 4; i++)
                o0.e[i] = (o0.e[i] > 0.f) ? o0.e[i] : expm1f(o0.e[i]);   // elu
            *(float4*)&g_x1[((size_t)(b*CC + c)*NN + n)*FIN2 + h*FF + 4*tx] = o0.f;
        } else {
            *(float4*)&g_o2[((size_t)sl*NN + n)*FF + 4*tx] = o0.f;
        }
    }
}

// ---------------- kernel 5: mean over heads ----------------
__global__ void reduce_mean_kernel(float* __restrict__ out){
    int idx = blockIdx.x*blockDim.x + threadIdx.x;          // B*C*N*F = 262144
    int f  = idx & 63;
    int nn = (idx >> 6) & (NN - 1);
    int bc = idx >> 16;                                     // NN*FF = 65536
    float sum = 0.f;
    #pragma unroll
    for (int h = 0; h < HH; h++)
        sum += g_o2[(((size_t)bc*HH + h)*NN + nn)*FF + f];
    out[idx] = sum * (1.f / HH);
}

// ---------------- launch ----------------
extern "C" void kernel_launch(void* const* d_in, const int* in_sizes, int n_in,
                              void* d_out, int out_size)
{
    const float* x   = (const float*)d_in[0];
    const int*   adj = (const int*)  d_in[1];
    const float* w1  = (const float*)d_in[2];
    const float* as1 = (const float*)d_in[3];
    const float* ad1 = (const float*)d_in[4];
    const float* w2  = (const float*)d_in[5];
    const float* as2 = (const float*)d_in[6];
    const float* ad2 = (const float*)d_in[7];
    float* out = (float*)d_out;

    cudaFuncSetAttribute(attn_kernel<true >, cudaFuncAttributeMaxDynamicSharedMemorySize, SM_ATTN);
    cudaFuncSetAttribute(attn_kernel<false>, cudaFuncAttributeMaxDynamicSharedMemorySize, SM_ATTN);

    pack_mask_kernel<<<dim3(NN, BB), 1024>>>(adj);

    gemm_sd_kernel<64,  false><<<dim3(NSL, 16), 256>>>(x, w1, as1, ad1);
    rowmax_kernel<<<dim3(NSL, 8), 256>>>();
    attn_kernel<true ><<<dim3(NSL, 16), 256, SM_ATTN>>>();

    gemm_sd_kernel<FIN2, true><<<dim3(NSL, 16), 256>>>(nullptr, w2, as2, ad2);
    rowmax_kernel<<<dim3(NSL, 8), 256>>>();
    attn_kernel<false><<<dim3(NSL, 16), 256, SM_ATTN>>>();

    reduce_mean_kernel<<<(BB*CC*NN*FF)/256, 256>>>(out);
}

// round 8
// speedup vs baseline: 1.0555x; 1.0555x over previous
#include <cuda_runtime.h>
#include <cfloat>
#include <math.h>

// Problem constants (fixed by the benchmark)
#define BB   2
#define CC   2
#define NN   1024
#define HH   8
#define FF   64
#define FIN2 (HH*FF)          // 512
#define NSL  (BB*CC*HH)       // 32 attention slices
#define L2E  1.4426950408889634f

// dynamic smem layout for attn kernel (bytes)
#define SM_HP    0            // float hp_s[64*64]            16384
#define SM_E2    16384        // float2 e2_s[64*66]           33792 (row stride 66)
#define SM_D     50176        // float d_s[1024]               4096
#define SM_SRML  54272        // float2 srml_s[64]              512
#define SM_LINV  54784        // float linv_s[64]               256
#define SM_ATTN  55040

// ---------------- scratch (device globals: allocation-free) ----------------
__device__ unsigned int g_mask[BB*NN*(NN/32)];            // packed valid-edge bits (incl self loops)
__device__ float g_hp[(size_t)NSL*NN*FF];                 // h_prime for current layer
__device__ float g_s [NSL*NN];                            // src scores
__device__ float g_d [NSL*NN];                            // dst scores
__device__ float g_rml[NSL*NN];                           // rowmax * log2(e)
__device__ float g_x1[(size_t)BB*CC*NN*FIN2];             // layer-1 output (elu, head-flattened)
__device__ float g_o2[(size_t)NSL*NN*FF];                 // layer-2 attention output (pre head-mean)

// ---------------- helpers ----------------
union f4u { float4 f; unsigned long long u[2]; float e[4]; };

__device__ __forceinline__ unsigned long long pack2(float a, float b){
    unsigned long long r;
    asm("mov.b64 %0, {%1,%2};" : "=l"(r) : "f"(a), "f"(b));
    return r;
}
__device__ __forceinline__ void ffma2(unsigned long long &d, unsigned long long a, unsigned long long b){
    asm("fma.rn.f32x2 %0, %1, %2, %0;" : "+l"(d) : "l"(a), "l"(b));
}
__device__ __forceinline__ float ex2f(float x){
    float r; asm("ex2.approx.f32 %0, %1;" : "=f"(r) : "f"(x)); return r;
}
__device__ __forceinline__ void cpasync16(unsigned smem, const void* g){
    asm volatile("cp.async.cg.shared.global [%0], [%1], 16;" :: "r"(smem), "l"(g));
}
__device__ __forceinline__ void cpasync_commit(){ asm volatile("cp.async.commit_group;"); }
__device__ __forceinline__ void cpasync_wait0(){ asm volatile("cp.async.wait_group 0;"); }

// ---------------- kernel 1: pack adjacency (+self loops) into bitmask ----------------
__global__ void pack_mask_kernel(const int* __restrict__ adj){
    int n = blockIdx.x, b = blockIdx.y, m = threadIdx.x;   // block of 1024 threads
    bool valid = (adj[((size_t)b*NN + n)*NN + m] != 0) || (m == n);
    unsigned bits = __ballot_sync(0xffffffffu, valid);
    if ((m & 31) == 0) g_mask[((size_t)b*NN + n)*32 + (m >> 5)] = bits;
}

// ---------------- kernel 2: h_prime = x @ w  (+ tanh -> s,d scores) ----------------
// grid (NSL, NN/64), block 256. Thread tile 4 rows x 4 feats, f32x2 FMAs.
template<int FIN, bool FROMX1>
__global__ __launch_bounds__(256, 3) void gemm_sd_kernel(
    const float* __restrict__ xin, const float* __restrict__ w,
    const float* __restrict__ a_src, const float* __restrict__ a_dst)
{
    __shared__ float xs[64*64];     // [n][k]
    __shared__ float ws[64*64];     // [k][f]
    __shared__ float as_s[64], ad_s[64];

    const int sl = blockIdx.x, n0 = blockIdx.y*64;
    const int b = sl/(CC*HH), c = (sl/HH)%CC, h = sl%HH;
    const int tid = threadIdx.x, lane = tid & 31;
    const int tx = tid & 15, ty = tid >> 4;        // feats 4tx.., rows 4ty..

    const float* x = FROMX1 ? (const float*)g_x1 : xin;
    const float* xbase = x + ((size_t)(b*CC + c)*NN + n0)*FIN;
    const float* wbase = w + (size_t)(c*HH + h)*FIN*FF;

    if (tid < 64){
        int ch = (c*HH + h)*FF;
        as_s[tid] = a_src[ch + tid];
        ad_s[tid] = a_dst[ch + tid];
    }

    f4u acc[4];
    #pragma unroll
    for (int j = 0; j < 4; j++){ acc[j].u[0] = 0ull; acc[j].u[1] = 0ull; }

    for (int kc = 0; kc < FIN/64; kc++){
        __syncthreads();
        // stage x tile [64n x 64k] (coalesced float4)
        #pragma unroll
        for (int p = 0; p < 4; p++){
            int n = (tid >> 4) + 16*p;
            ((float4*)xs)[n*16 + (tid & 15)] =
                *(const float4*)&xbase[(size_t)n*FIN + kc*64 + 4*(tid & 15)];
        }
        // stage w tile [64k x 64f] (contiguous)
        const float4* wsrc = (const float4*)(wbase + (size_t)kc*64*FF);
        #pragma unroll
        for (int q = 0; q < 4; q++) ((float4*)ws)[tid + 256*q] = wsrc[tid + 256*q];
        __syncthreads();

        const float4* xs4 = (const float4*)xs;
        const float4* ws4 = (const float4*)ws;
        #pragma unroll
        for (int kk = 0; kk < 16; kk++){
            f4u xr[4];
            #pragma unroll
            for (int j = 0; j < 4; j++) xr[j].f = xs4[(4*ty + j)*16 + kk];
            #pragma unroll
            for (int i = 0; i < 4; i++){
                f4u wv; wv.f = ws4[(4*kk + i)*16 + tx];
                #pragma unroll
                for (int j = 0; j < 4; j++){
                    unsigned long long xx = pack2(xr[j].e[i], xr[j].e[i]);
                    ffma2(acc[j].u[0], wv.u[0], xx);
                    ffma2(acc[j].u[1], wv.u[1], xx);
                }
            }
        }
    }

    // epilogue: write h_prime + tanh-weighted scores
    #pragma unroll
    for (int j = 0; j < 4; j++){
        const int n = n0 + 4*ty + j;
        *(float4*)&g_hp[((size_t)sl*NN + n)*FF + 4*tx] = acc[j].f;
        float sp = 0.f, dp = 0.f;
        #pragma unroll
        for (int i = 0; i < 4; i++){
            float t = tanhf(acc[j].e[i]);
            sp = fmaf(t, as_s[4*tx + i], sp);
            dp = fmaf(t, ad_s[4*tx + i], dp);
        }
        #pragma unroll
        for (int o = 8; o; o >>= 1){
            sp += __shfl_xor_sync(0xffffffffu, sp, o);
            dp += __shfl_xor_sync(0xffffffffu, dp, o);
        }
        if ((lane & 15) == 0){ g_s[sl*NN + n] = sp; g_d[sl*NN + n] = dp; }
    }
}

// ---------------- kernel 3: exact row max (leaky is monotone => leaky(s + dmax)) ----------------
// grid (NSL, NN/128), block 256 (8 warps x 16 rows).
__global__ __launch_bounds__(256) void rowmax_kernel(){
    __shared__ float d_sw[1024];                 // d rotated for conflict-free column scans
    const int sl = blockIdx.x, n0 = blockIdx.y*128;
    const int b = sl/(CC*HH);
    const int tid = threadIdx.x, lane = tid & 31, wrp = tid >> 5;

    for (int i = tid; i < 1024; i += 256){
        int w = i >> 5, j = i & 31;
        d_sw[(w << 5) + ((j + w) & 31)] = g_d[sl*NN + i];
    }
    __syncthreads();

    const unsigned* mb = g_mask + (size_t)b*NN*32;
    for (int r = 0; r < 16; r++){
        const int n = n0 + wrp*16 + r;
        unsigned word = mb[(size_t)n*32 + lane];
        float dm = -FLT_MAX;
        #pragma unroll
        for (int i = 0; i < 32; i++){
            float v = d_sw[(lane << 5) + ((i + lane) & 31)];
            if ((word >> i) & 1u) dm = fmaxf(dm, v);
        }
        #pragma unroll
        for (int o = 16; o; o >>= 1) dm = fmaxf(dm, __shfl_xor_sync(0xffffffffu, dm, o));
        if (lane == 0){
            float s = g_s[sl*NN + n];
            float r0 = s + dm; r0 = (r0 >= 0.f) ? r0 : 0.2f*r0;   // leaky(max) = max(leaky)
            g_rml[sl*NN + n] = r0 * L2E;
        }
    }
}

// ---------------- kernel 4: masked softmax + P @ h_prime (single pass, no rescale) ----------------
// grid (NSL, NN/64), block 256, 3 CTAs/SM, dynamic smem. 64 rows x 64 feats, m-tile 64.
// e stored DUPLICATED as float2{e,e} -> accumulate needs zero pack instructions:
// per 4-k chunk: 12 LDS.128 + 32 ffma2 (44 issue slots / 64 MACs).
template<bool LAYER1>
__global__ __launch_bounds__(256, 3) void attn_kernel(){
    extern __shared__ char smdyn[];
    float*  hp_s   = (float*) (smdyn + SM_HP);     // [m][f]
    float2* e2_s   = (float2*)(smdyn + SM_E2);     // [row][m] dup, stride 66
    float*  d_s    = (float*) (smdyn + SM_D);
    float2* srml_s = (float2*)(smdyn + SM_SRML);   // {s, rml}
    float*  linv_s = (float*) (smdyn + SM_LINV);

    const int sl = blockIdx.x, n0 = blockIdx.y*64;
    const int b = sl/(CC*HH), c = (sl/HH)%CC, h = sl%HH;
    const int tid = threadIdx.x, lane = tid & 31, wrp = tid >> 5;
    const int tx = tid & 15, ty = tid >> 4;
    const int row0 = wrp*8;

    for (int i = tid; i < 1024; i += 256) d_s[i] = g_d[sl*NN + i];
    if (tid < 64)
        srml_s[tid] = make_float2(g_s[sl*NN + n0 + tid], g_rml[sl*NN + n0 + tid]);

    float lsum[8];
    #pragma unroll
    for (int r = 0; r < 8; r++) lsum[r] = 0.f;

    f4u acc[4];
    #pragma unroll
    for (int j = 0; j < 4; j++){ acc[j].u[0] = 0ull; acc[j].u[1] = 0ull; }

    const unsigned* mbase = g_mask + ((size_t)b*NN + n0)*32;
    const unsigned hp_smem = (unsigned)__cvta_generic_to_shared(hp_s);

    __syncthreads();                             // d_s/srml_s ready

    for (int t = 0; t < 16; t++){
        const int m0 = t*64;

        // issue async copy of h_prime tile (overlaps with score phase below)
        const float4* hsrc = (const float4*)(g_hp + ((size_t)sl*NN + m0)*FF);
        #pragma unroll
        for (int q = 0; q < 4; q++)
            cpasync16(hp_smem + (tid + 256*q)*16, hsrc + tid + 256*q);
        cpasync_commit();

        // coalesced mask fetch: lanes 0..15 hold 8 rows x 2 words for this warp
        unsigned mword = 0u;
        if (lane < 16)
            mword = mbase[(size_t)(row0 + (lane >> 1))*32 + t*2 + (lane & 1)];

        // --- score phase (writes duplicated e pairs) ---
        const float d0 = d_s[m0 + lane];
        const float d1 = d_s[m0 + lane + 32];
        #pragma unroll
        for (int r = 0; r < 8; r++){
            const int row = row0 + r;
            unsigned mwa = __shfl_sync(0xffffffffu, mword, 2*r);
            unsigned mwb = __shfl_sync(0xffffffffu, mword, 2*r + 1);
            float2 sr = srml_s[row];
            float x0 = sr.x + d0; x0 = (x0 >= 0.f) ? x0 : 0.2f*x0;   // leaky_relu(0.2)
            float x1 = sr.x + d1; x1 = (x1 >= 0.f) ? x1 : 0.2f*x1;
            float e0 = ((mwa >> lane) & 1u) ? ex2f(fmaf(x0, L2E, -sr.y)) : 0.f;
            float e1 = ((mwb >> lane) & 1u) ? ex2f(fmaf(x1, L2E, -sr.y)) : 0.f;
            lsum[r] += e0 + e1;
            e2_s[row*66 + lane]      = make_float2(e0, e0);
            e2_s[row*66 + lane + 32] = make_float2(e1, e1);
        }

        cpasync_wait0();
        __syncthreads();                         // e2_s + hp_s ready

        // --- accumulate phase: P-tile @ h-tile, pack-free f32x2 register GEMM ---
        const float4* hp4 = (const float4*)hp_s;
        const float4* e4  = (const float4*)(smdyn + SM_E2);   // row stride 33 float4
        #pragma unroll
        for (int kk = 0; kk < 16; kk++){
            f4u wv[4];
            #pragma unroll
            for (int i = 0; i < 4; i++) wv[i].f = hp4[(4*kk + i)*16 + tx];
            #pragma unroll
            for (int j = 0; j < 4; j++){
                const float4* er = e4 + (4*ty + j)*33 + 2*kk;
                f4u ea, eb; ea.f = er[0]; eb.f = er[1];        // (e,e) pairs for k..k+3
                ffma2(acc[j].u[0], wv[0].u[0], ea.u[0]);
                ffma2(acc[j].u[1], wv[0].u[1], ea.u[0]);
                ffma2(acc[j].u[0], wv[1].u[0], ea.u[1]);
                ffma2(acc[j].u[1], wv[1].u[1], ea.u[1]);
                ffma2(acc[j].u[0], wv[2].u[0], eb.u[0]);
                ffma2(acc[j].u[1], wv[2].u[1], eb.u[0]);
                ffma2(acc[j].u[0], wv[3].u[0], eb.u[1]);
                ffma2(acc[j].u[1], wv[3].u[1], eb.u[1]);
            }
        }
        __syncthreads();                         // protect hp_s/e2_s before next tile
    }

    // reduce row sums (per-lane partials) and invert
    #pragma unroll
    for (int r = 0; r < 8; r++){
        float v = lsum[r];
        #pragma unroll
        for (int o = 16; o; o >>= 1) v += __shfl_xor_sync(0xffffffffu, v, o);
        if (lane == 0) linv_s[row0 + r] = 1.f / v;
    }
    __syncthreads();

    // epilogue
    #pragma unroll
    for (int j = 0; j < 4; j++){
        const int row = 4*ty + j, n = n0 + row;
        const float inv = linv_s[row];
        f4u o0;
        #pragma unroll
        for (int i = 0; i < 4; i++) o0.e[i] = acc[j].e[i] * inv;
        if (LAYER1){
            #pragma unroll
            for (int i = 0; i < 4; i++)
                o0.e[i] = (o0.e[i] > 0.f) ? o0.e[i] : expm1f(o0.e[i]);   // elu
            *(float4*)&g_x1[((size_t)(b*CC + c)*NN + n)*FIN2 + h*FF + 4*tx] = o0.f;
        } else {
            *(float4*)&g_o2[((size_t)sl*NN + n)*FF + 4*tx] = o0.f;
        }
    }
}

// ---------------- kernel 5: mean over heads ----------------
__global__ void reduce_mean_kernel(float* __restrict__ out){
    int idx = blockIdx.x*blockDim.x + threadIdx.x;          // B*C*N*F = 262144
    int f  = idx & 63;
    int nn = (idx >> 6) & (NN - 1);
    int bc = idx >> 16;                                     // NN*FF = 65536
    float sum = 0.f;
    #pragma unroll
    for (int h = 0; h < HH; h++)
        sum += g_o2[(((size_t)bc*HH + h)*NN + nn)*FF + f];
    out[idx] = sum * (1.f / HH);
}

// ---------------- launch ----------------
extern "C" void kernel_launch(void* const* d_in, const int* in_sizes, int n_in,
                              void* d_out, int out_size)
{
    const float* x   = (const float*)d_in[0];
    const int*   adj = (const int*)  d_in[1];
    const float* w1  = (const float*)d_in[2];
    const float* as1 = (const float*)d_in[3];
    const float* ad1 = (const float*)d_in[4];
    const float* w2  = (const float*)d_in[5];
    const float* as2 = (const float*)d_in[6];
    const float* ad2 = (const float*)d_in[7];
    float* out = (float*)d_out;

    cudaFuncSetAttribute(attn_kernel<true >, cudaFuncAttributeMaxDynamicSharedMemorySize, SM_ATTN);
    cudaFuncSetAttribute(attn_kernel<false>, cudaFuncAttributeMaxDynamicSharedMemorySize, SM_ATTN);

    pack_mask_kernel<<<dim3(NN, BB), 1024>>>(adj);

    gemm_sd_kernel<64,  false><<<dim3(NSL, 16), 256>>>(x, w1, as1, ad1);
    rowmax_kernel<<<dim3(NSL, 8), 256>>>();
    attn_kernel<true ><<<dim3(NSL, 16), 256, SM_ATTN>>>();

    gemm_sd_kernel<FIN2, true><<<dim3(NSL, 16), 256>>>(nullptr, w2, as2, ad2);
    rowmax_kernel<<<dim3(NSL, 8), 256>>>();
    attn_kernel<false><<<dim3(NSL, 16), 256, SM_ATTN>>>();

    reduce_mean_kernel<<<(BB*CC*NN*FF)/256, 256>>>(out);
}

// round 9
// speedup vs baseline: 1.2854x; 1.2178x over previous
#include <cuda_runtime.h>
#include <cfloat>
#include <math.h>

// Problem constants (fixed by the benchmark)
#define BB   2
#define CC   2
#define NN   1024
#define HH   8
#define FF   64
#define FIN2 (HH*FF)          // 512
#define NSL  (BB*CC*HH)       // 32 attention slices
#define L2E  1.4426950408889634f

// ---------------- scratch (device globals: allocation-free) ----------------
__device__ unsigned int g_mask[BB*NN*(NN/32)];            // packed valid-edge bits (incl self loops)
__device__ float g_hp[(size_t)NSL*NN*FF];                 // h_prime for current layer
__device__ float g_s [NSL*NN];                            // src scores
__device__ float g_d [NSL*NN];                            // dst scores
__device__ float g_rml[NSL*NN];                           // rowmax * log2(e)
__device__ float g_x1[(size_t)BB*CC*NN*FIN2];             // layer-1 output (elu, head-flattened)
__device__ float g_o2[(size_t)NSL*NN*FF];                 // layer-2 attention output (pre head-mean)

// ---------------- helpers ----------------
union f4u { float4 f; unsigned long long u[2]; float e[4]; };

__device__ __forceinline__ unsigned long long pack2(float a, float b){
    unsigned long long r;
    asm("mov.b64 %0, {%1,%2};" : "=l"(r) : "f"(a), "f"(b));
    return r;
}
__device__ __forceinline__ void ffma2(unsigned long long &d, unsigned long long a, unsigned long long b){
    asm("fma.rn.f32x2 %0, %1, %2, %0;" : "+l"(d) : "l"(a), "l"(b));
}
__device__ __forceinline__ float ex2f(float x){
    float r; asm("ex2.approx.f32 %0, %1;" : "=f"(r) : "f"(x)); return r;
}
__device__ __forceinline__ void cpasync16(unsigned smem, const void* g){
    asm volatile("cp.async.cg.shared.global [%0], [%1], 16;" :: "r"(smem), "l"(g));
}
__device__ __forceinline__ void cpasync_commit(){ asm volatile("cp.async.commit_group;"); }
__device__ __forceinline__ void cpasync_wait0(){ asm volatile("cp.async.wait_group 0;"); }

// ---------------- kernel 1: pack adjacency (+self loops) into bitmask ----------------
__global__ void pack_mask_kernel(const int* __restrict__ adj){
    int n = blockIdx.x, b = blockIdx.y, m = threadIdx.x;   // block of 1024 threads
    bool valid = (adj[((size_t)b*NN + n)*NN + m] != 0) || (m == n);
    unsigned bits = __ballot_sync(0xffffffffu, valid);
    if ((m & 31) == 0) g_mask[((size_t)b*NN + n)*32 + (m >> 5)] = bits;
}

// ---------------- kernel 2: h_prime = x @ w  (+ tanh -> s,d scores) ----------------
// grid (NSL, NN/64), block 256. Thread tile 4 rows x 4 feats, f32x2 FMAs.
template<int FIN, bool FROMX1>
__global__ __launch_bounds__(256, 3) void gemm_sd_kernel(
    const float* __restrict__ xin, const float* __restrict__ w,
    const float* __restrict__ a_src, const float* __restrict__ a_dst)
{
    __shared__ float xs[64*64];     // [n][k]
    __shared__ float ws[64*64];     // [k][f]
    __shared__ float as_s[64], ad_s[64];

    const int sl = blockIdx.x, n0 = blockIdx.y*64;
    const int b = sl/(CC*HH), c = (sl/HH)%CC, h = sl%HH;
    const int tid = threadIdx.x, lane = tid & 31;
    const int tx = tid & 15, ty = tid >> 4;        // feats 4tx.., rows 4ty..

    const float* x = FROMX1 ? (const float*)g_x1 : xin;
    const float* xbase = x + ((size_t)(b*CC + c)*NN + n0)*FIN;
    const float* wbase = w + (size_t)(c*HH + h)*FIN*FF;

    if (tid < 64){
        int ch = (c*HH + h)*FF;
        as_s[tid] = a_src[ch + tid];
        ad_s[tid] = a_dst[ch + tid];
    }

    f4u acc[4];
    #pragma unroll
    for (int j = 0; j < 4; j++){ acc[j].u[0] = 0ull; acc[j].u[1] = 0ull; }

    for (int kc = 0; kc < FIN/64; kc++){
        __syncthreads();
        // stage x tile [64n x 64k] (coalesced float4)
        #pragma unroll
        for (int p = 0; p < 4; p++){
            int n = (tid >> 4) + 16*p;
            ((float4*)xs)[n*16 + (tid & 15)] =
                *(const float4*)&xbase[(size_t)n*FIN + kc*64 + 4*(tid & 15)];
        }
        // stage w tile [64k x 64f] (contiguous)
        const float4* wsrc = (const float4*)(wbase + (size_t)kc*64*FF);
        #pragma unroll
        for (int q = 0; q < 4; q++) ((float4*)ws)[tid + 256*q] = wsrc[tid + 256*q];
        __syncthreads();

        const float4* xs4 = (const float4*)xs;
        const float4* ws4 = (const float4*)ws;
        #pragma unroll
        for (int kk = 0; kk < 16; kk++){
            f4u xr[4];
            #pragma unroll
            for (int j = 0; j < 4; j++) xr[j].f = xs4[(4*ty + j)*16 + kk];
            #pragma unroll
            for (int i = 0; i < 4; i++){
                f4u wv; wv.f = ws4[(4*kk + i)*16 + tx];
                #pragma unroll
                for (int j = 0; j < 4; j++){
                    unsigned long long xx = pack2(xr[j].e[i], xr[j].e[i]);
                    ffma2(acc[j].u[0], wv.u[0], xx);
                    ffma2(acc[j].u[1], wv.u[1], xx);
                }
            }
        }
    }

    // epilogue: write h_prime + tanh-weighted scores
    #pragma unroll
    for (int j = 0; j < 4; j++){
        const int n = n0 + 4*ty + j;
        *(float4*)&g_hp[((size_t)sl*NN + n)*FF + 4*tx] = acc[j].f;
        float sp = 0.f, dp = 0.f;
        #pragma unroll
        for (int i = 0; i < 4; i++){
            float t = tanhf(acc[j].e[i]);
            sp = fmaf(t, as_s[4*tx + i], sp);
            dp = fmaf(t, ad_s[4*tx + i], dp);
        }
        #pragma unroll
        for (int o = 8; o; o >>= 1){
            sp += __shfl_xor_sync(0xffffffffu, sp, o);
            dp += __shfl_xor_sync(0xffffffffu, dp, o);
        }
        if ((lane & 15) == 0){ g_s[sl*NN + n] = sp; g_d[sl*NN + n] = dp; }
    }
}

// ---------------- kernel 3: exact row max (leaky is monotone => leaky(s + dmax)) ----------------
// grid (NSL, NN/128), block 256 (8 warps x 16 rows).
__global__ __launch_bounds__(256) void rowmax_kernel(){
    __shared__ float d_sw[1024];                 // d rotated for conflict-free column scans
    const int sl = blockIdx.x, n0 = blockIdx.y*128;
    const int b = sl/(CC*HH);
    const int tid = threadIdx.x, lane = tid & 31, wrp = tid >> 5;

    for (int i = tid; i < 1024; i += 256){
        int w = i >> 5, j = i & 31;
        d_sw[(w << 5) + ((j + w) & 31)] = g_d[sl*NN + i];
    }
    __syncthreads();

    const unsigned* mb = g_mask + (size_t)b*NN*32;
    for (int r = 0; r < 16; r++){
        const int n = n0 + wrp*16 + r;
        unsigned word = mb[(size_t)n*32 + lane];
        float dm = -FLT_MAX;
        #pragma unroll
        for (int i = 0; i < 32; i++){
            float v = d_sw[(lane << 5) + ((i + lane) & 31)];
            if ((word >> i) & 1u) dm = fmaxf(dm, v);
        }
        #pragma unroll
        for (int o = 16; o; o >>= 1) dm = fmaxf(dm, __shfl_xor_sync(0xffffffffu, dm, o));
        if (lane == 0){
            float s = g_s[sl*NN + n];
            float r0 = s + dm; r0 = (r0 >= 0.f) ? r0 : 0.2f*r0;   // leaky(max) = max(leaky)
            g_rml[sl*NN + n] = r0 * L2E;
        }
    }
}

// ---------------- kernel 4: masked softmax + P @ h_prime (single pass, no rescale) ----------------
// grid (NSL, NN/64), block 256, 4 CTAs/SM (single wave over 148 SMs).
// 64 rows x 64 feats per block, m-tile 64.
// Scores: warp w owns rows 8w..8w+7 (mask words fetched coalesced by lanes 0-15).
// h_prime tile loaded via cp.async, overlapped with the score phase.
// Accumulate: thread (tx,ty) owns rows 4ty..4ty+3 x feats 4tx..4tx+3, f32x2 FMAs.
template<bool LAYER1>
__global__ __launch_bounds__(256, 4) void attn_kernel(){
    __shared__ float hp_s[64*64];                // [m][f] 16 KB
    __shared__ float e_s[64*68];                 // [row][m] padded, 17 KB
    __shared__ float d_s[1024];
    __shared__ float s_s[64];
    __shared__ float rml_s[64];
    __shared__ float linv_s[64];

    const int sl = blockIdx.x, n0 = blockIdx.y*64;
    const int b = sl/(CC*HH), c = (sl/HH)%CC, h = sl%HH;
    const int tid = threadIdx.x, lane = tid & 31, wrp = tid >> 5;
    const int tx = tid & 15, ty = tid >> 4;
    const int row0 = wrp*8;

    for (int i = tid; i < 1024; i += 256) d_s[i] = g_d[sl*NN + i];
    if (tid < 64){
        s_s[tid]   = g_s  [sl*NN + n0 + tid];
        rml_s[tid] = g_rml[sl*NN + n0 + tid];
    }

    float lsum[8];
    #pragma unroll
    for (int r = 0; r < 8; r++) lsum[r] = 0.f;

    f4u acc[4];
    #pragma unroll
    for (int j = 0; j < 4; j++){ acc[j].u[0] = 0ull; acc[j].u[1] = 0ull; }

    const unsigned* mbase = g_mask + ((size_t)b*NN + n0)*32;
    const unsigned hp_smem = (unsigned)__cvta_generic_to_shared(hp_s);

    __syncthreads();                             // d_s/s_s/rml_s ready

    for (int t = 0; t < 16; t++){
        const int m0 = t*64;

        // issue async copy of h_prime tile (overlaps with score phase below)
        const float4* hsrc = (const float4*)(g_hp + ((size_t)sl*NN + m0)*FF);
        #pragma unroll
        for (int q = 0; q < 4; q++)
            cpasync16(hp_smem + (tid + 256*q)*16, hsrc + tid + 256*q);
        cpasync_commit();

        // coalesced mask fetch: lanes 0..15 hold 8 rows x 2 words for this warp
        unsigned mword = 0u;
        if (lane < 16)
            mword = mbase[(size_t)(row0 + (lane >> 1))*32 + t*2 + (lane & 1)];

        // --- score phase ---
        const float d0 = d_s[m0 + lane];
        const float d1 = d_s[m0 + lane + 32];
        #pragma unroll
        for (int r = 0; r < 8; r++){
            const int row = row0 + r;
            unsigned mwa = __shfl_sync(0xffffffffu, mword, 2*r);
            unsigned mwb = __shfl_sync(0xffffffffu, mword, 2*r + 1);
            float s = s_s[row], rml = rml_s[row];
            float x0 = s + d0; x0 = (x0 >= 0.f) ? x0 : 0.2f*x0;    // leaky_relu(0.2)
            float x1 = s + d1; x1 = (x1 >= 0.f) ? x1 : 0.2f*x1;
            float e0 = ((mwa >> lane) & 1u) ? ex2f(fmaf(x0, L2E, -rml)) : 0.f;
            float e1 = ((mwb >> lane) & 1u) ? ex2f(fmaf(x1, L2E, -rml)) : 0.f;
            lsum[r] += e0 + e1;
            e_s[row*68 + lane]      = e0;
            e_s[row*68 + lane + 32] = e1;
        }

        cpasync_wait0();
        __syncthreads();                         // e_s + hp_s ready

        // --- accumulate phase: P-tile @ h-tile, f32x2 register GEMM ---
        const float4* hp4 = (const float4*)hp_s;
        const float4* e4  = (const float4*)e_s;
        #pragma unroll
        for (int kk = 0; kk < 16; kk++){
            f4u ev[4];
            #pragma unroll
            for (int j = 0; j < 4; j++) ev[j].f = e4[(4*ty + j)*17 + kk];
            #pragma unroll
            for (int i = 0; i < 4; i++){
                f4u wv; wv.f = hp4[(4*kk + i)*16 + tx];
                #pragma unroll
                for (int j = 0; j < 4; j++){
                    unsigned long long ee = pack2(ev[j].e[i], ev[j].e[i]);
                    ffma2(acc[j].u[0], wv.u[0], ee);
                    ffma2(acc[j].u[1], wv.u[1], ee);
                }
            }
        }
        __syncthreads();                         // protect hp_s/e_s before next tile
    }

    // reduce row sums (per-lane partials) and invert
    #pragma unroll
    for (int r = 0; r < 8; r++){
        float v = lsum[r];
        #pragma unroll
        for (int o = 16; o; o >>= 1) v += __shfl_xor_sync(0xffffffffu, v, o);
        if (lane == 0) linv_s[row0 + r] = 1.f / v;
    }
    __syncthreads();

    // epilogue
    #pragma unroll
    for (int j = 0; j < 4; j++){
        const int row = 4*ty + j, n = n0 + row;
        const float inv = linv_s[row];
        f4u o0;
        #pragma unroll
        for (int i = 0; i < 4; i++) o0.e[i] = acc[j].e[i] * inv;
        if (LAYER1){
            #pragma unroll
            for (int i = 0; i < 4; i++)
                o0.e[i] = (o0.e[i] > 0.f) ? o0.e[i] : expm1f(o0.e[i]);   // elu
            *(float4*)&g_x1[((size_t)(b*CC + c)*NN + n)*FIN2 + h*FF + 4*tx] = o0.f;
        } else {
            *(float4*)&g_o2[((size_t)sl*NN + n)*FF + 4*tx] = o0.f;
        }
    }
}

// ---------------- kernel 5: mean over heads ----------------
__global__ void reduce_mean_kernel(float* __restrict__ out){
    int idx = blockIdx.x*blockDim.x + threadIdx.x;          // B*C*N*F = 262144
    int f  = idx & 63;
    int nn = (idx >> 6) & (NN - 1);
    int bc = idx >> 16;                                     // NN*FF = 65536
    float sum = 0.f;
    #pragma unroll
    for (int h = 0; h < HH; h++)
        sum += g_o2[(((size_t)bc*HH + h)*NN + nn)*FF + f];
    out[idx] = sum * (1.f / HH);
}

// ---------------- launch ----------------
extern "C" void kernel_launch(void* const* d_in, const int* in_sizes, int n_in,
                              void* d_out, int out_size)
{
    const float* x   = (const float*)d_in[0];
    const int*   adj = (const int*)  d_in[1];
    const float* w1  = (const float*)d_in[2];
    const float* as1 = (const float*)d_in[3];
    const float* ad1 = (const float*)d_in[4];
    const float* w2  = (const float*)d_in[5];
    const float* as2 = (const float*)d_in[6];
    const float* ad2 = (const float*)d_in[7];
    float* out = (float*)d_out;

    pack_mask_kernel<<<dim3(NN, BB), 1024>>>(adj);

    gemm_sd_kernel<64,  false><<<dim3(NSL, 16), 256>>>(x, w1, as1, ad1);
    rowmax_kernel<<<dim3(NSL, 8), 256>>>();
    attn_kernel<true ><<<dim3(NSL, 16), 256>>>();

    gemm_sd_kernel<FIN2, true><<<dim3(NSL, 16), 256>>>(nullptr, w2, as2, ad2);
    rowmax_kernel<<<dim3(NSL, 8), 256>>>();
    attn_kernel<false><<<dim3(NSL, 16), 256>>>();

    reduce_mean_kernel<<<(BB*CC*NN*FF)/256, 256>>>(out);
}